// round 9
// baseline (speedup 1.0000x reference)
#include <cuda_runtime.h>
#include <math.h>

// Problem constants
#define B    32
#define T    256
#define D    256
#define HID  1024
#define G3   3072
#define OO   256
#define ALPHA 0.001f
#define ONEMA 0.999f

#define NBLK 128          // one block per 8 output columns (128*8 = 1024)
#define THR  512          // 16 warps = 16 k-chunks

typedef unsigned long long u64;

// ---------------- static device scratch (allocation-free) ----------------
__device__ float g_WT0[(HID + D) * G3];        // 1280 x 3072 k-major
__device__ float g_WT1[(2 * HID) * G3];        // 2048 x 3072 k-major
__device__ float g_xT[(size_t)T * D * 32];     // transposed input [t*D+d][b]
__device__ float g_o0[(size_t)T * HID * 32];   // layer0 events [t][j][b]
__device__ float g_sh[2][HID * 32];            // h = o*c, [j][b], double-buffered
__device__ unsigned g_bar_cnt;
__device__ volatile unsigned g_bar_gen;

__device__ __forceinline__ float sigmoidf_(float v) { return 1.0f / (1.0f + expf(-v)); }

__device__ __forceinline__ void ffma2(u64& d, u64 a, u64 b) {
    asm("fma.rn.f32x2 %0, %1, %2, %0;" : "+l"(d) : "l"(a), "l"(b));
}
__device__ __forceinline__ u64 packdup(float a) {
    u64 r; unsigned ua = __float_as_uint(a);
    asm("mov.b64 %0, {%1, %1};" : "=l"(r) : "r"(ua));
    return r;
}
__device__ __forceinline__ void unpack2(u64 v, float& lo, float& hi) {
    unsigned l, h;
    asm("mov.b64 {%0, %1}, %2;" : "=r"(l), "=r"(h) : "l"(v));
    lo = __uint_as_float(l); hi = __uint_as_float(h);
}

// ---------------- grid-wide barrier (all NBLK blocks resident) ----------------
__device__ __forceinline__ void gbar(unsigned target) {
    __syncthreads();
    if (threadIdx.x == 0) {
        __threadfence();
        unsigned old = atomicAdd(&g_bar_cnt, 1u);
        if (old == NBLK - 1u) {
            g_bar_cnt = 0u;
            __threadfence();
            g_bar_gen = target;
        } else {
            while (g_bar_gen != target) { }
        }
        __threadfence();
    }
    __syncthreads();
}

// ---------------- weight pack: dst[k][col] = src[col][k] ----------------
__global__ void pack_kernel(const float* __restrict__ src, int dstSel, int K, int rowOff) {
    __shared__ float tile[32][33];
    float* dst = dstSel ? g_WT1 : g_WT0;
    int kBase = blockIdx.x * 32;
    int colBase = blockIdx.y * 32;
    int tx = threadIdx.x, ty = threadIdx.y;   // (32, 8)
#pragma unroll
    for (int i = 0; i < 32; i += 8) {
        int col = colBase + ty + i;
        tile[ty + i][tx] = src[(size_t)col * K + kBase + tx];
    }
    __syncthreads();
#pragma unroll
    for (int i = 0; i < 32; i += 8) {
        int k = kBase + ty + i;
        dst[(size_t)(k + rowOff) * G3 + colBase + tx] = tile[tx][ty + i];
    }
}

// ---------------- x transpose: x[b][t][d] -> g_xT[t*D+d][b] ----------------
__global__ void xpose_kernel(const float* __restrict__ x) {
    __shared__ float tile[32][33];
    int col0 = blockIdx.x * 32;               // td tile
    int tx = threadIdx.x, ty = threadIdx.y;   // (32, 8)
#pragma unroll
    for (int i = 0; i < 32; i += 8) {
        int b = ty + i;
        tile[b][tx] = x[(size_t)b * (T * D) + col0 + tx];
    }
    __syncthreads();
#pragma unroll
    for (int i = 0; i < 32; i += 8) {
        int td = col0 + ty + i;
        g_xT[(size_t)td * 32 + tx] = tile[tx][ty + i];
    }
}

// ---------------- state + barrier init ----------------
__global__ void init_state_kernel() {
    int idx = blockIdx.x * blockDim.x + threadIdx.x;
    if (idx < B * HID) { g_sh[0][idx] = 0.0f; g_sh[1][idx] = 0.0f; }
    if (idx == 0) { g_bar_cnt = 0u; g_bar_gen = 0u; }
}

// store 2 gates (8 floats each) into exchange buffer row, pitch 17
__device__ __forceinline__ void store16(float* p, const u64* a, const u64* b) {
    float lo, hi;
    unpack2(a[0], lo, hi); p[0] = lo; p[1] = hi;
    unpack2(a[1], lo, hi); p[2] = lo; p[3] = hi;
    unpack2(a[2], lo, hi); p[4] = lo; p[5] = hi;
    unpack2(a[3], lo, hi); p[6] = lo; p[7] = hi;
    unpack2(b[0], lo, hi); p[8]  = lo; p[9]  = hi;
    unpack2(b[1], lo, hi); p[10] = lo; p[11] = hi;
    unpack2(b[2], lo, hi); p[12] = lo; p[13] = hi;
    unpack2(b[3], lo, hi); p[14] = lo; p[15] = hi;
}

// ---------------- persistent scan kernel ----------------
// grid = 128 blocks, each owns 8 j-columns; warp w = contiguous k-chunk w.
// Pure-x warps (no hidden rows) precompute step t+1 during step t's update
// window. Per-gate chunk sums stay in serial s=0..15 order (bitwise stable).
// c/o/i states live in the 256 update threads' registers.
template <int LAYER>
__global__ __launch_bounds__(THR, 1) void scan_kernel(
    const float* __restrict__ bias,
    const float* __restrict__ thr_raw,
    float* __restrict__ hs, float* __restrict__ cs,
    float* __restrict__ os, float* __restrict__ is_)
{
    constexpr int KX    = (LAYER == 0) ? D : HID;    // x-part K
    constexpr int KT    = HID + KX;                  // total K
    constexpr int CK    = KT / 16;                   // 80 / 128 per warp-chunk
    constexpr int CH_HI = (LAYER == 0) ? 13 : 8;     // chunks with hidden rows
    constexpr int CX_LO = (LAYER == 0) ? 12 : 8;     // chunks with x rows
    const float* __restrict__ WT = (LAYER == 0) ? g_WT0 : g_WT1;

    extern __shared__ float smem[];
    float* s_w = smem;                               // [KT][24]
    float* s_p = smem + KT * 24;                     // [16][32] pitch 17 exchange

    const int tid  = threadIdx.x;
    const int lane = tid & 31;                       // = batch in GEMM
    const int wrp  = tid >> 5;                       // = k-chunk index
    const int jb   = blockIdx.x * 8;                 // block's 8 j-columns

    // ---- stage weights into smem once ----
    for (int i = tid; i < KT * 6; i += THR) {
        int k = i / 6, c = i - k * 6;
        int g = c >> 1, half = c & 1;
        float4 v = *(const float4*)(WT + (size_t)k * G3 + g * HID + jb + half * 4);
        ((float4*)(s_w + k * 24))[c] = v;
    }

    // update-phase constants + register state (tid<256: fj=tid&7, fb=tid>>3)
    const int fj = tid & 7;
    const int fb = tid >> 3;
    const int jg = jb + fj;
    float thv = 0.f, bU = 0.f, bR = 0.f, bC = 0.f;
    float rc = 0.f, ro = 0.f, riu = 0.f, rir = 0.f, ric = 0.f;   // c,o,i state
    if (tid < 256) {
        thv = sigmoidf_(thr_raw[jg]);
        bU = bias[jg]; bR = bias[HID + jg]; bC = bias[2 * HID + jg];
    }
    __syncthreads();

    const int k0 = wrp * CK;
    int hEnd = HID - k0;                             // hidden rows in this chunk
    if (hEnd < 0) hEnd = 0;
    if (hEnd > CK) hEnd = CK;
    const int xCnt = CK - hEnd;
    const int kx0 = k0 + hEnd - HID;                 // x-row start (valid iff xCnt>0)
    const bool pureX = (hEnd == 0);                  // warp needs no h at all
    float* myrow = s_p + (wrp * 32 + lane) * 17;

    u64 aU[4], aR[4], aCH[4], aCX[4];
#pragma unroll
    for (int i = 0; i < 4; i++) { aU[i] = 0; aR[i] = 0; aCH[i] = 0; aCX[i] = 0; }

    // ---- pure-x prologue: compute step-0 partials (static data) ----
    if (pureX) {
        const float* ax = (LAYER == 0)
            ? g_xT + (size_t)kx0 * 32 + lane
            : g_o0 + (size_t)kx0 * 32 + lane;
        const longlong2* wr = (const longlong2*)(s_w + (size_t)k0 * 24);
#pragma unroll 4
        for (int kk = 0; kk < CK; kk++) {
            u64 aa = packdup(ax[kk * 32]);
            longlong2 p0 = wr[0], p1 = wr[1], p2 = wr[2];
            longlong2 p3 = wr[3], p4 = wr[4], p5 = wr[5];
            ffma2(aU[0], (u64)p0.x, aa); ffma2(aU[1], (u64)p0.y, aa);
            ffma2(aU[2], (u64)p1.x, aa); ffma2(aU[3], (u64)p1.y, aa);
            ffma2(aR[0], (u64)p2.x, aa); ffma2(aR[1], (u64)p2.y, aa);
            ffma2(aR[2], (u64)p3.x, aa); ffma2(aR[3], (u64)p3.y, aa);
            ffma2(aCX[0], (u64)p4.x, aa); ffma2(aCX[1], (u64)p4.y, aa);
            ffma2(aCX[2], (u64)p5.x, aa); ffma2(aCX[3], (u64)p5.y, aa);
            wr += 6;
        }
    }

    unsigned gen = 0;

    for (int t = 0; t < T; t++) {
        const float* __restrict__ shR = g_sh[t & 1];
        float* __restrict__ shW = g_sh[(t & 1) ^ 1];

        // ---- GEMM (non-pure-x warps; round-8 order: hidden rows then x rows) ----
        if (!pureX) {
#pragma unroll
            for (int i = 0; i < 4; i++) { aU[i] = 0; aR[i] = 0; aCH[i] = 0; aCX[i] = 0; }
            const longlong2* wr = (const longlong2*)(s_w + (size_t)k0 * 24);
            {   // hidden rows -> aCH
                const float* ah = shR + (size_t)k0 * 32 + lane;
#pragma unroll 4
                for (int kk = 0; kk < hEnd; kk++) {
                    u64 aa = packdup(ah[kk * 32]);
                    longlong2 p0 = wr[0], p1 = wr[1], p2 = wr[2];
                    longlong2 p3 = wr[3], p4 = wr[4], p5 = wr[5];
                    ffma2(aU[0], (u64)p0.x, aa); ffma2(aU[1], (u64)p0.y, aa);
                    ffma2(aU[2], (u64)p1.x, aa); ffma2(aU[3], (u64)p1.y, aa);
                    ffma2(aR[0], (u64)p2.x, aa); ffma2(aR[1], (u64)p2.y, aa);
                    ffma2(aR[2], (u64)p3.x, aa); ffma2(aR[3], (u64)p3.y, aa);
                    ffma2(aCH[0], (u64)p4.x, aa); ffma2(aCH[1], (u64)p4.y, aa);
                    ffma2(aCH[2], (u64)p5.x, aa); ffma2(aCH[3], (u64)p5.y, aa);
                    wr += 6;
                }
            }
            if (xCnt > 0) {   // mixed chunk: x rows -> aCX (after hidden, k-ascending)
                const float* ax = (LAYER == 0)
                    ? g_xT + ((size_t)t * D + kx0) * 32 + lane
                    : g_o0 + ((size_t)t * HID + kx0) * 32 + lane;
#pragma unroll 4
                for (int kk = 0; kk < xCnt; kk++) {
                    u64 aa = packdup(ax[kk * 32]);
                    longlong2 p0 = wr[0], p1 = wr[1], p2 = wr[2];
                    longlong2 p3 = wr[3], p4 = wr[4], p5 = wr[5];
                    ffma2(aU[0], (u64)p0.x, aa); ffma2(aU[1], (u64)p0.y, aa);
                    ffma2(aU[2], (u64)p1.x, aa); ffma2(aU[3], (u64)p1.y, aa);
                    ffma2(aR[0], (u64)p2.x, aa); ffma2(aR[1], (u64)p2.y, aa);
                    ffma2(aR[2], (u64)p3.x, aa); ffma2(aR[3], (u64)p3.y, aa);
                    ffma2(aCX[0], (u64)p4.x, aa); ffma2(aCX[1], (u64)p4.y, aa);
                    ffma2(aCX[2], (u64)p5.x, aa); ffma2(aCX[3], (u64)p5.y, aa);
                    wr += 6;
                }
            }
        }
        // pure-x warps: partials already in aU/aR/aCX from previous iteration

        // ---- exchange round 1: U, R ----
        store16(myrow, aU, aR);
        __syncthreads();
        float su = 0.f, sr = 0.f;
        if (tid < 256) {
#pragma unroll
            for (int s = 0; s < 16; s++) {
                const float* q = s_p + (s * 32 + fb) * 17;
                su += q[fj];
                sr += q[8 + fj];
            }
        }
        __syncthreads();

        // ---- exchange round 2: CH, CX ----
        store16(myrow, aCH, aCX);
        __syncthreads();
        float sch = 0.f, scx = 0.f;
        if (tid < 256) {
#pragma unroll
            for (int s = 0; s < 16; s++) {
                const float* q = s_p + (s * 32 + fb) * 17;
                if (s < CH_HI) sch += q[fj];
                if (s >= CX_LO) scx += q[8 + fj];
            }
        }

        // ---- pure-x warps: precompute step t+1 while update threads work ----
        if (pureX) {
            if (t + 1 < T) {
#pragma unroll
                for (int i = 0; i < 4; i++) { aU[i] = 0; aR[i] = 0; aCX[i] = 0; }
                const float* ax = (LAYER == 0)
                    ? g_xT + ((size_t)(t + 1) * D + kx0) * 32 + lane
                    : g_o0 + ((size_t)(t + 1) * HID + kx0) * 32 + lane;
                const longlong2* wr = (const longlong2*)(s_w + (size_t)k0 * 24);
#pragma unroll 4
                for (int kk = 0; kk < CK; kk++) {
                    u64 aa = packdup(ax[kk * 32]);
                    longlong2 p0 = wr[0], p1 = wr[1], p2 = wr[2];
                    longlong2 p3 = wr[3], p4 = wr[4], p5 = wr[5];
                    ffma2(aU[0], (u64)p0.x, aa); ffma2(aU[1], (u64)p0.y, aa);
                    ffma2(aU[2], (u64)p1.x, aa); ffma2(aU[3], (u64)p1.y, aa);
                    ffma2(aR[0], (u64)p2.x, aa); ffma2(aR[1], (u64)p2.y, aa);
                    ffma2(aR[2], (u64)p3.x, aa); ffma2(aR[3], (u64)p3.y, aa);
                    ffma2(aCX[0], (u64)p4.x, aa); ffma2(aCX[1], (u64)p4.y, aa);
                    ffma2(aCX[2], (u64)p5.x, aa); ffma2(aCX[3], (u64)p5.y, aa);
                    wr += 6;
                }
            }
        } else if (tid < 256) {
            // ---- EGRU update: one (b, j) per thread, register state ----
            float niu = ALPHA * riu + ONEMA * (su + bU);
            float u = sigmoidf_(niu);
            float nir = ALPHA * rir + ONEMA * (sr + bR);
            float r = sigmoidf_(nir);
            float nic = ALPHA * ric + ONEMA * (scx + r * sch + bC);
            float z = tanhf(nic);

            float creset = rc - ro * thv;
            float nc = (1.0f - u) * creset + u * z;
            float no = (nc - thv > 0.0f) ? 1.0f : 0.0f;

            rc = nc; ro = no; riu = niu; rir = nir; ric = nic;

            shW[jg * 32 + fb] = no * nc;

            if (LAYER == 0) {
                g_o0[((size_t)t * HID + jg) * 32 + fb] = no;
            } else {
                size_t ho = (size_t)t * (B * HID) + fb * HID + jg;
                hs[ho] = no * nc;
                cs[ho] = nc;
                os[ho] = no;
                size_t io = (size_t)t * (B * G3) + (size_t)fb * G3 + jg;
                is_[io] = niu;
                is_[io + HID] = nir;
                is_[io + 2 * HID] = nic;
            }
        }
        gbar(++gen);
    }
}

// ---------------- softmax head ----------------
__global__ void head_kernel(const float* __restrict__ hLast,
                            const float* __restrict__ w_out,
                            const float* __restrict__ b_out,
                            float* __restrict__ pred)
{
    __shared__ float sh_h[HID];
    __shared__ float red[OO];
    int b = blockIdx.x, tid = threadIdx.x;
    for (int i = tid; i < HID; i += OO) sh_h[i] = hLast[b * HID + i];
    __syncthreads();

    float acc = 0.0f;
    const float* w = w_out + (size_t)tid * HID;
#pragma unroll 4
    for (int k = 0; k < HID; k++) acc += w[k] * sh_h[k];
    float logit = acc + b_out[tid];

    red[tid] = logit; __syncthreads();
    for (int s = 128; s > 0; s >>= 1) { if (tid < s) red[tid] = fmaxf(red[tid], red[tid + s]); __syncthreads(); }
    float mx = red[0]; __syncthreads();
    float e = expf(logit - mx);
    red[tid] = e; __syncthreads();
    for (int s = 128; s > 0; s >>= 1) { if (tid < s) red[tid] += red[tid + s]; __syncthreads(); }
    float sum = red[0];
    pred[b * OO + tid] = e / sum;
}

// ---------------- launch ----------------
extern "C" void kernel_launch(void* const* d_in, const int* in_sizes, int n_in,
                              void* d_out, int out_size) {
    const float* x     = (const float*)d_in[0];
    const float* w_ih0 = (const float*)d_in[1];
    const float* w_hh0 = (const float*)d_in[2];
    const float* bias0 = (const float*)d_in[3];
    const float* thr0  = (const float*)d_in[4];
    const float* w_ih1 = (const float*)d_in[6];
    const float* w_hh1 = (const float*)d_in[7];
    const float* bias1 = (const float*)d_in[8];
    const float* thr1  = (const float*)d_in[9];
    const float* w_out = (const float*)d_in[11];
    const float* b_out = (const float*)d_in[12];

    float* out  = (float*)d_out;
    float* pred = out;
    float* hs   = out + B * OO;
    float* cs   = hs + (size_t)T * B * HID;
    float* os   = cs + (size_t)T * B * HID;
    float* is_  = os + (size_t)T * B * HID;

    const int SMEM0 = (HID + D) * 24 * 4 + 16 * 32 * 17 * 4;    // 157,696 B
    const int SMEM1 = (2 * HID) * 24 * 4 + 16 * 32 * 17 * 4;    // 231,424 B
    cudaFuncSetAttribute(scan_kernel<0>, cudaFuncAttributeMaxDynamicSharedMemorySize, SMEM0);
    cudaFuncSetAttribute(scan_kernel<1>, cudaFuncAttributeMaxDynamicSharedMemorySize, SMEM1);

    dim3 tpt(32, 8);
    pack_kernel<<<dim3(HID / 32, G3 / 32), tpt>>>(w_hh0, 0, HID, 0);
    pack_kernel<<<dim3(D / 32, G3 / 32), tpt>>>(w_ih0, 0, D, HID);
    xpose_kernel<<<T * D / 32, tpt>>>(x);
    init_state_kernel<<<(B * HID + 255) / 256, 256>>>();
    scan_kernel<0><<<NBLK, THR, SMEM0>>>(bias0, thr0, nullptr, nullptr, nullptr, nullptr);

    pack_kernel<<<dim3(HID / 32, G3 / 32), tpt>>>(w_hh1, 1, HID, 0);
    pack_kernel<<<dim3(HID / 32, G3 / 32), tpt>>>(w_ih1, 1, HID, HID);
    init_state_kernel<<<(B * HID + 255) / 256, 256>>>();
    scan_kernel<1><<<NBLK, THR, SMEM1>>>(bias1, thr1, hs, cs, os, is_);

    head_kernel<<<B, OO>>>(hs + (size_t)(T - 1) * B * HID, w_out, b_out, pred);
}

// round 10
// speedup vs baseline: 1.5090x; 1.5090x over previous
#include <cuda_runtime.h>
#include <math.h>

// Problem constants
#define B    32
#define T    256
#define D    256
#define HID  1024
#define G3   3072
#define OO   256
#define ALPHA 0.001f
#define ONEMA 0.999f

#define NBLK 128          // one block per 8 output columns (128*8 = 1024)
#define THR  512          // 16 warps = 16 k-chunks

typedef unsigned long long u64;

// ---------------- static device scratch (allocation-free) ----------------
__device__ float g_WT0[(HID + D) * G3];        // 1280 x 3072 k-major
__device__ float g_WT1[(2 * HID) * G3];        // 2048 x 3072 k-major
__device__ float g_xT[(size_t)T * D * 32];     // transposed input [t*D+d][b]
__device__ float g_o0[(size_t)T * HID * 32];   // layer0 events [t][j][b]
__device__ float g_sh[2][HID * 32];            // h = o*c, [j][b], double-buffered
__device__ unsigned g_bar_cnt;
__device__ volatile unsigned g_bar_gen;

__device__ __forceinline__ float sigmoidf_(float v) { return 1.0f / (1.0f + expf(-v)); }

__device__ __forceinline__ void ffma2(u64& d, u64 a, u64 b) {
    asm("fma.rn.f32x2 %0, %1, %2, %0;" : "+l"(d) : "l"(a), "l"(b));
}
__device__ __forceinline__ u64 packdup(float a) {
    u64 r; unsigned ua = __float_as_uint(a);
    asm("mov.b64 %0, {%1, %1};" : "=l"(r) : "r"(ua));
    return r;
}
__device__ __forceinline__ void unpack2(u64 v, float& lo, float& hi) {
    unsigned l, h;
    asm("mov.b64 {%0, %1}, %2;" : "=r"(l), "=r"(h) : "l"(v));
    lo = __uint_as_float(l); hi = __uint_as_float(h);
}

// ---------------- grid-wide barrier (all NBLK blocks resident) ----------------
__device__ __forceinline__ void gbar(unsigned target) {
    __syncthreads();
    if (threadIdx.x == 0) {
        __threadfence();
        unsigned old = atomicAdd(&g_bar_cnt, 1u);
        if (old == NBLK - 1u) {
            g_bar_cnt = 0u;
            __threadfence();
            g_bar_gen = target;
        } else {
            while (g_bar_gen != target) { }
        }
        __threadfence();
    }
    __syncthreads();
}

// ---------------- weight pack: dst[k][col] = src[col][k] ----------------
__global__ void pack_kernel(const float* __restrict__ src, int dstSel, int K, int rowOff) {
    __shared__ float tile[32][33];
    float* dst = dstSel ? g_WT1 : g_WT0;
    int kBase = blockIdx.x * 32;
    int colBase = blockIdx.y * 32;
    int tx = threadIdx.x, ty = threadIdx.y;   // (32, 8)
#pragma unroll
    for (int i = 0; i < 32; i += 8) {
        int col = colBase + ty + i;
        tile[ty + i][tx] = src[(size_t)col * K + kBase + tx];
    }
    __syncthreads();
#pragma unroll
    for (int i = 0; i < 32; i += 8) {
        int k = kBase + ty + i;
        dst[(size_t)(k + rowOff) * G3 + colBase + tx] = tile[tx][ty + i];
    }
}

// ---------------- x transpose: x[b][t][d] -> g_xT[t*D+d][b] ----------------
__global__ void xpose_kernel(const float* __restrict__ x) {
    __shared__ float tile[32][33];
    int col0 = blockIdx.x * 32;               // td tile
    int tx = threadIdx.x, ty = threadIdx.y;   // (32, 8)
#pragma unroll
    for (int i = 0; i < 32; i += 8) {
        int b = ty + i;
        tile[b][tx] = x[(size_t)b * (T * D) + col0 + tx];
    }
    __syncthreads();
#pragma unroll
    for (int i = 0; i < 32; i += 8) {
        int td = col0 + ty + i;
        g_xT[(size_t)td * 32 + tx] = tile[tx][ty + i];
    }
}

// ---------------- state + barrier init ----------------
__global__ void init_state_kernel() {
    int idx = blockIdx.x * blockDim.x + threadIdx.x;
    if (idx < B * HID) { g_sh[0][idx] = 0.0f; g_sh[1][idx] = 0.0f; }
    if (idx == 0) { g_bar_cnt = 0u; g_bar_gen = 0u; }
}

// store 2 gates (8 floats each) into exchange buffer row, pitch 17
__device__ __forceinline__ void store16(float* p, const u64* a, const u64* b) {
    float lo, hi;
    unpack2(a[0], lo, hi); p[0] = lo; p[1] = hi;
    unpack2(a[1], lo, hi); p[2] = lo; p[3] = hi;
    unpack2(a[2], lo, hi); p[4] = lo; p[5] = hi;
    unpack2(a[3], lo, hi); p[6] = lo; p[7] = hi;
    unpack2(b[0], lo, hi); p[8]  = lo; p[9]  = hi;
    unpack2(b[1], lo, hi); p[10] = lo; p[11] = hi;
    unpack2(b[2], lo, hi); p[12] = lo; p[13] = hi;
    unpack2(b[3], lo, hi); p[14] = lo; p[15] = hi;
}

// One k-segment of GEMM with 8-deep activation prefetch.
// cnt must be a multiple of 8 (all chunk splits satisfy this).
// Accumulation order identical to serial k-ascending (bitwise stable).
#define GEMM_SEG(cnt, aptr, AC)                                              \
    for (int kt = 0; kt < (cnt); kt += 8) {                                  \
        float a8[8];                                                         \
        _Pragma("unroll")                                                    \
        for (int i = 0; i < 8; i++) a8[i] = (aptr)[(size_t)(kt + i) * 32];   \
        _Pragma("unroll")                                                    \
        for (int i = 0; i < 8; i++) {                                        \
            u64 aa = packdup(a8[i]);                                         \
            longlong2 p0 = wr[0], p1 = wr[1], p2 = wr[2];                    \
            longlong2 p3 = wr[3], p4 = wr[4], p5 = wr[5];                    \
            ffma2(aU[0], (u64)p0.x, aa); ffma2(aU[1], (u64)p0.y, aa);        \
            ffma2(aU[2], (u64)p1.x, aa); ffma2(aU[3], (u64)p1.y, aa);        \
            ffma2(aR[0], (u64)p2.x, aa); ffma2(aR[1], (u64)p2.y, aa);        \
            ffma2(aR[2], (u64)p3.x, aa); ffma2(aR[3], (u64)p3.y, aa);        \
            ffma2(AC[0], (u64)p4.x, aa); ffma2(AC[1], (u64)p4.y, aa);        \
            ffma2(AC[2], (u64)p5.x, aa); ffma2(AC[3], (u64)p5.y, aa);        \
            wr += 6;                                                         \
        }                                                                    \
    }

// ---------------- persistent scan kernel ----------------
// grid = 128 blocks, each owns 8 j-columns; warp w = contiguous k-chunk w.
// All 16 warps GEMM concurrently each step (round-8 structure).
// Per-gate chunk sums in serial s=0..15 order. Register-resident c/o/i state.
template <int LAYER>
__global__ __launch_bounds__(THR, 1) void scan_kernel(
    const float* __restrict__ bias,
    const float* __restrict__ thr_raw,
    float* __restrict__ hs, float* __restrict__ cs,
    float* __restrict__ os, float* __restrict__ is_)
{
    constexpr int KX    = (LAYER == 0) ? D : HID;    // x-part K
    constexpr int KT    = HID + KX;                  // total K
    constexpr int CK    = KT / 16;                   // 80 / 128 per warp-chunk
    constexpr int CH_HI = (LAYER == 0) ? 13 : 8;     // chunks with hidden rows
    constexpr int CX_LO = (LAYER == 0) ? 12 : 8;     // chunks with x rows
    const float* __restrict__ WT = (LAYER == 0) ? g_WT0 : g_WT1;

    extern __shared__ float smem[];
    float* s_w = smem;                               // [KT][24]
    float* s_p = smem + KT * 24;                     // [16][32] pitch 17 exchange

    const int tid  = threadIdx.x;
    const int lane = tid & 31;                       // = batch in GEMM
    const int wrp  = tid >> 5;                       // = k-chunk index
    const int jb   = blockIdx.x * 8;                 // block's 8 j-columns

    // ---- stage weights into smem once ----
    for (int i = tid; i < KT * 6; i += THR) {
        int k = i / 6, c = i - k * 6;
        int g = c >> 1, half = c & 1;
        float4 v = *(const float4*)(WT + (size_t)k * G3 + g * HID + jb + half * 4);
        ((float4*)(s_w + k * 24))[c] = v;
    }

    // update-phase constants + register state (tid<256: fj=tid&7, fb=tid>>3)
    const int fj = tid & 7;
    const int fb = tid >> 3;
    const int jg = jb + fj;
    float thv = 0.f, bU = 0.f, bR = 0.f, bC = 0.f;
    float rc = 0.f, ro = 0.f, riu = 0.f, rir = 0.f, ric = 0.f;   // c,o,i state
    if (tid < 256) {
        thv = sigmoidf_(thr_raw[jg]);
        bU = bias[jg]; bR = bias[HID + jg]; bC = bias[2 * HID + jg];
    }
    __syncthreads();

    const int k0 = wrp * CK;
    int hEnd = HID - k0;                             // hidden rows in this chunk
    if (hEnd < 0) hEnd = 0;
    if (hEnd > CK) hEnd = CK;
    const int xCnt = CK - hEnd;
    const int kx0 = k0 + hEnd - HID;                 // x-row start (valid iff xCnt>0)
    float* myrow = s_p + (wrp * 32 + lane) * 17;

    unsigned gen = 0;

    for (int t = 0; t < T; t++) {
        const float* __restrict__ shR = g_sh[t & 1];
        float* __restrict__ shW = g_sh[(t & 1) ^ 1];

        // ---- GEMM: serial over this warp's contiguous chunk, 8-deep prefetch ----
        u64 aU[4], aR[4], aCH[4], aCX[4];
#pragma unroll
        for (int i = 0; i < 4; i++) { aU[i] = 0; aR[i] = 0; aCH[i] = 0; aCX[i] = 0; }

        const longlong2* wr = (const longlong2*)(s_w + (size_t)k0 * 24);
        if (hEnd > 0) {                              // hidden rows -> aCH
            const float* ah = shR + (size_t)k0 * 32 + lane;
            GEMM_SEG(hEnd, ah, aCH)
        }
        if (xCnt > 0) {                              // x rows -> aCX
            const float* ax = (LAYER == 0)
                ? g_xT + ((size_t)t * D + kx0) * 32 + lane
                : g_o0 + ((size_t)t * HID + kx0) * 32 + lane;
            GEMM_SEG(xCnt, ax, aCX)
        }

        // ---- exchange round 1: U, R ----
        store16(myrow, aU, aR);
        __syncthreads();
        float su = 0.f, sr = 0.f;
        if (tid < 256) {
#pragma unroll
            for (int s = 0; s < 16; s++) {
                const float* q = s_p + (s * 32 + fb) * 17;
                su += q[fj];
                sr += q[8 + fj];
            }
        }
        __syncthreads();

        // ---- exchange round 2: CH, CX ----
        store16(myrow, aCH, aCX);
        __syncthreads();
        float sch = 0.f, scx = 0.f;
        if (tid < 256) {
#pragma unroll
            for (int s = 0; s < 16; s++) {
                const float* q = s_p + (s * 32 + fb) * 17;
                if (s < CH_HI) sch += q[fj];
                if (s >= CX_LO) scx += q[8 + fj];
            }
        }

        // ---- EGRU update: one (b, j) per thread, register state ----
        if (tid < 256) {
            float niu = ALPHA * riu + ONEMA * (su + bU);
            float u = sigmoidf_(niu);
            float nir = ALPHA * rir + ONEMA * (sr + bR);
            float r = sigmoidf_(nir);
            float nic = ALPHA * ric + ONEMA * (scx + r * sch + bC);
            float z = tanhf(nic);

            float creset = rc - ro * thv;
            float nc = (1.0f - u) * creset + u * z;
            float no = (nc - thv > 0.0f) ? 1.0f : 0.0f;

            rc = nc; ro = no; riu = niu; rir = nir; ric = nic;

            shW[jg * 32 + fb] = no * nc;

            if (LAYER == 0) {
                g_o0[((size_t)t * HID + jg) * 32 + fb] = no;
            } else {
                size_t ho = (size_t)t * (B * HID) + fb * HID + jg;
                hs[ho] = no * nc;
                cs[ho] = nc;
                os[ho] = no;
                size_t io = (size_t)t * (B * G3) + (size_t)fb * G3 + jg;
                is_[io] = niu;
                is_[io + HID] = nir;
                is_[io + 2 * HID] = nic;
            }
        }
        gbar(++gen);
    }
}

// ---------------- softmax head ----------------
__global__ void head_kernel(const float* __restrict__ hLast,
                            const float* __restrict__ w_out,
                            const float* __restrict__ b_out,
                            float* __restrict__ pred)
{
    __shared__ float sh_h[HID];
    __shared__ float red[OO];
    int b = blockIdx.x, tid = threadIdx.x;
    for (int i = tid; i < HID; i += OO) sh_h[i] = hLast[b * HID + i];
    __syncthreads();

    float acc = 0.0f;
    const float* w = w_out + (size_t)tid * HID;
#pragma unroll 4
    for (int k = 0; k < HID; k++) acc += w[k] * sh_h[k];
    float logit = acc + b_out[tid];

    red[tid] = logit; __syncthreads();
    for (int s = 128; s > 0; s >>= 1) { if (tid < s) red[tid] = fmaxf(red[tid], red[tid + s]); __syncthreads(); }
    float mx = red[0]; __syncthreads();
    float e = expf(logit - mx);
    red[tid] = e; __syncthreads();
    for (int s = 128; s > 0; s >>= 1) { if (tid < s) red[tid] += red[tid + s]; __syncthreads(); }
    float sum = red[0];
    pred[b * OO + tid] = e / sum;
}

// ---------------- launch ----------------
extern "C" void kernel_launch(void* const* d_in, const int* in_sizes, int n_in,
                              void* d_out, int out_size) {
    const float* x     = (const float*)d_in[0];
    const float* w_ih0 = (const float*)d_in[1];
    const float* w_hh0 = (const float*)d_in[2];
    const float* bias0 = (const float*)d_in[3];
    const float* thr0  = (const float*)d_in[4];
    const float* w_ih1 = (const float*)d_in[6];
    const float* w_hh1 = (const float*)d_in[7];
    const float* bias1 = (const float*)d_in[8];
    const float* thr1  = (const float*)d_in[9];
    const float* w_out = (const float*)d_in[11];
    const float* b_out = (const float*)d_in[12];

    float* out  = (float*)d_out;
    float* pred = out;
    float* hs   = out + B * OO;
    float* cs   = hs + (size_t)T * B * HID;
    float* os   = cs + (size_t)T * B * HID;
    float* is_  = os + (size_t)T * B * HID;

    const int SMEM0 = (HID + D) * 24 * 4 + 16 * 32 * 17 * 4;    // 157,696 B
    const int SMEM1 = (2 * HID) * 24 * 4 + 16 * 32 * 17 * 4;    // 231,424 B
    cudaFuncSetAttribute(scan_kernel<0>, cudaFuncAttributeMaxDynamicSharedMemorySize, SMEM0);
    cudaFuncSetAttribute(scan_kernel<1>, cudaFuncAttributeMaxDynamicSharedMemorySize, SMEM1);

    dim3 tpt(32, 8);
    pack_kernel<<<dim3(HID / 32, G3 / 32), tpt>>>(w_hh0, 0, HID, 0);
    pack_kernel<<<dim3(D / 32, G3 / 32), tpt>>>(w_ih0, 0, D, HID);
    xpose_kernel<<<T * D / 32, tpt>>>(x);
    init_state_kernel<<<(B * HID + 255) / 256, 256>>>();
    scan_kernel<0><<<NBLK, THR, SMEM0>>>(bias0, thr0, nullptr, nullptr, nullptr, nullptr);

    pack_kernel<<<dim3(HID / 32, G3 / 32), tpt>>>(w_hh1, 1, HID, 0);
    pack_kernel<<<dim3(HID / 32, G3 / 32), tpt>>>(w_ih1, 1, HID, HID);
    init_state_kernel<<<(B * HID + 255) / 256, 256>>>();
    scan_kernel<1><<<NBLK, THR, SMEM1>>>(bias1, thr1, hs, cs, os, is_);

    head_kernel<<<B, OO>>>(hs + (size_t)(T - 1) * B * HID, w_out, b_out, pred);
}